// round 7
// baseline (speedup 1.0000x reference)
#include <cuda_runtime.h>
#include <cuda_fp16.h>
#include <cstdint>

// Problem constants
static constexpr int Nb = 4, C = 12, GD = 8, GH = 16, GW = 16;
static constexpr int H = 1024, W = 1024;
static constexpr int HW = H * W;
static constexpr int GRID_PER_N = C * GD * GH * GW;   // 24576 floats

// Main grid (half) layout [z][y*16+x][c], z-stride padded to 3076 halfs.
static constexpr int ZSTRIDE_H = GH * GW * C + 4;     // 3076 halfs
static constexpr int MAIN_HALFS = GD * ZSTRIDE_H;     // 24608 halfs = 49216 B

// Per-row y-lerped buffer: [z][x][c] halfs, z-slab = 192 data + 24 pad = 216
// halfs (108 words ≡ 12 mod 32 → the 8 z levels hit disjoint bank pairs for
// the per-pixel LDS.64 bursts). Double-buffered.
static constexpr int YZS = GW * C + 24;               // 216 halfs
static constexpr int YBUF_HALFS = GD * YZS;           // 1728 halfs
static constexpr int SMEM_HALFS = MAIN_HALFS + 2 * YBUF_HALFS;
static constexpr int SMEM_BYTES = SMEM_HALFS * 2;     // 56128 B

static constexpr int THREADS = 512;                   // 1 px/thread
static constexpr int ROWS_PER_BLOCK = 4;

__device__ __forceinline__ __half2 u2h(unsigned u) {
    return *reinterpret_cast<__half2*>(&u);
}

// Fetch 48 B (both x-corners, 12 ch) from the y-lerped buffer, x-lerp -> 6 half2.
__device__ __forceinline__ void fetch_xlerp(const __half* buf, int off,
                                            __half2 wx0, __half2 wx1,
                                            __half2* r) {
    const uint2* p = reinterpret_cast<const uint2*>(buf + off);
    uint2 a0 = p[0], a1 = p[1], a2 = p[2];   // corner ix0
    uint2 b0 = p[3], b1 = p[4], b2 = p[5];   // corner ix0+1 (maybe pad, wx1=0)
    r[0] = __hfma2(u2h(b0.x), wx1, __hmul2(u2h(a0.x), wx0));
    r[1] = __hfma2(u2h(b0.y), wx1, __hmul2(u2h(a0.y), wx0));
    r[2] = __hfma2(u2h(b1.x), wx1, __hmul2(u2h(a1.x), wx0));
    r[3] = __hfma2(u2h(b1.y), wx1, __hmul2(u2h(a1.y), wx0));
    r[4] = __hfma2(u2h(b2.x), wx1, __hmul2(u2h(a2.x), wx0));
    r[5] = __hfma2(u2h(b2.y), wx1, __hmul2(u2h(a2.y), wx0));
}

__global__ __launch_bounds__(THREADS, 3)
void slice_kernel(const float* __restrict__ grid,
                  const float* __restrict__ guide,
                  float* __restrict__ out) {
    extern __shared__ __align__(16) __half sh[];
    __half* yb0 = sh + MAIN_HALFS;                 // double buffers
    __half* yb1 = yb0 + YBUF_HALFS;

    const int n   = blockIdx.y;
    const int tid = threadIdx.x;

    // ---- Load grid[n] (c,z,y,x) f32 -> smem half (z, y*16+x, c) ----
    const float* g = grid + (size_t)n * GRID_PER_N;
    #pragma unroll
    for (int i = tid * 4; i < GRID_PER_N; i += THREADS * 4) {
        float4 v = *reinterpret_cast<const float4*>(g + i);
        int c   = i >> 11;
        int zyx = i & 2047;
        int z   = zyx >> 8;
        int yx  = zyx & 255;
        int base = z * ZSTRIDE_H + yx * C + c;
        sh[base]         = __float2half_rn(v.x);
        sh[base + C]     = __float2half_rn(v.y);
        sh[base + 2 * C] = __float2half_rn(v.z);
        sh[base + 3 * C] = __float2half_rn(v.w);
    }
    __syncthreads();

    // Geometry: blockIdx.x = rowblock*2 + x-segment; 512 consecutive px.
    const int seg    = blockIdx.x & 1;
    const int rowblk = blockIdx.x >> 1;
    const int x      = seg * 512 + tid;

    // x cell + weights (edge: corner1 weight forced to 0, junk data zeroed pad)
    float tx = (x + 0.5f) * (1.0f / 64.0f) - 0.5f;
    float fx = floorf(tx);
    int  ifx = (int)fx;
    float bx = tx - fx;
    float w1f = (ifx < 0 || ifx >= GW - 1) ? 0.0f : bx;
    const __half2 wx0 = __float2half2_rn(1.0f - w1f);
    const __half2 wx1 = __float2half2_rn(w1f);
    const int xoff = min(max(ifx, 0), GW - 1) * C;

    const float* gd = guide + (size_t)n * HW + x;
    float* ob = out + (size_t)n * C * HW + x;

    #pragma unroll 1
    for (int j = 0; j < ROWS_PER_BLOCK; ++j) {
        const int row = rowblk * ROWS_PER_BLOCK + j;
        __half* yb = (j & 1) ? yb1 : yb0;

        // y weights (uniform across block)
        float ty = (row + 0.5f) * (16.0f / 1024.0f) - 0.5f;
        float fy = floorf(ty);
        float by = ty - fy;
        int ify = (int)fy;
        int iy0 = min(max(ify, 0), GH - 1);
        int iy1 = min(max(ify + 1, 0), GH - 1);
        const int yo0 = iy0 * (GW * C), yo1 = iy1 * (GW * C);
        const __half2 wy0 = __float2half2_rn(1.0f - by);
        const __half2 wy1 = __float2half2_rn(by);

        // ---- Cooperative y-lerp: grid[z][iy*][x][c] -> yb[z][x][c] ----
        // 768 data half2 + 96 pad half2 (zeroed: junk*0 could be NaN).
        #pragma unroll
        for (int e = tid; e < 768 + 96; e += THREADS) {
            if (e < 768) {
                int z = e / 96;             // 96 half2 per z slab (192 halfs)
                int r = e - z * 96;
                int src = z * ZSTRIDE_H + 2 * r;
                unsigned a = *reinterpret_cast<const unsigned*>(sh + src + yo0);
                unsigned b = *reinterpret_cast<const unsigned*>(sh + src + yo1);
                __half2 v = __hfma2(u2h(b), wy1, __hmul2(u2h(a), wy0));
                *reinterpret_cast<__half2*>(yb + z * YZS + 2 * r) = v;
            } else {
                int p = e - 768;            // 96 pad half2 (12 per z slab)
                int z = p / 12;
                int r = p - z * 12;
                *reinterpret_cast<__half2*>(yb + z * YZS + 192 + 2 * r) =
                    __float2half2_rn(0.0f);
            }
        }
        __syncthreads();

        // ---- Per-pixel: z cell from guide, 2 fetches, x+z lerp ----
        float gz = gd[(size_t)row * W];
        float tz = gz * 8.0f - 0.5f;
        float fz = floorf(tz);
        float bz = tz - fz;
        int ifz = (int)fz;
        int iz0 = min(max(ifz, 0), GD - 1);
        int iz1 = min(max(ifz + 1, 0), GD - 1);
        const __half2 wz0 = __float2half2_rn(1.0f - bz);
        const __half2 wz1 = __float2half2_rn(bz);

        __half2 v0[6], v1[6];
        fetch_xlerp(yb, iz0 * YZS + xoff, wx0, wx1, v0);
        fetch_xlerp(yb, iz1 * YZS + xoff, wx0, wx1, v1);

        float* obr = ob + (size_t)row * W;
        #pragma unroll
        for (int k = 0; k < 6; ++k) {
            __half2 vz = __hfma2(v1[k], wz1, __hmul2(v0[k], wz0));
            float2 f = __half22float2(vz);
            obr[(size_t)(2 * k) * HW]     = f.x;
            obr[(size_t)(2 * k + 1) * HW] = f.y;
        }
    }
}

extern "C" void kernel_launch(void* const* d_in, const int* in_sizes, int n_in,
                              void* d_out, int out_size) {
    const float* grid  = (const float*)d_in[0];   // (4,12,8,16,16) f32
    const float* guide = (const float*)d_in[1];   // (4,1,1024,1024) f32
    float* out = (float*)d_out;                   // (4,12,1024,1024) f32

    cudaFuncSetAttribute(slice_kernel,
                         cudaFuncAttributeMaxDynamicSharedMemorySize,
                         SMEM_BYTES);

    dim3 gridDim((H / ROWS_PER_BLOCK) * 2, Nb);   // (512, 4) = 2048 blocks
    slice_kernel<<<gridDim, THREADS, SMEM_BYTES>>>(grid, guide, out);
}

// round 8
// speedup vs baseline: 1.7333x; 1.7333x over previous
#include <cuda_runtime.h>
#include <cuda_fp16.h>
#include <cstdint>

// Problem constants
static constexpr int Nb = 4, C = 12, GD = 8, GH = 16, GW = 16;
static constexpr int H = 1024, W = 1024;
static constexpr int HW = H * W;
static constexpr int GRID_PER_N = C * GD * GH * GW;   // 24576 floats

// Main grid (half) layout [z][y*16+x][c], z-stride padded to 3076 halfs
// (1538 words == 2 mod 32 -> 8 z levels on disjoint bank pairs).
static constexpr int ZSTRIDE_H = GH * GW * C + 4;     // 3076 halfs
static constexpr int MAIN_HALFS = GD * ZSTRIDE_H;     // 24608 halfs

// Per-row y-lerped buffer: [row][z][x][c]; z-slab = 192 data + 24 pad = 216
// halfs (108 words == 12 mod 32 -> 8 z levels on disjoint bank pairs).
static constexpr int YZS = GW * C + 24;               // 216 halfs
static constexpr int YROW = GD * YZS;                 // 1728 halfs per row
static constexpr int ROWS_PER_BLOCK = 4;
static constexpr int YBUF_HALFS = ROWS_PER_BLOCK * YROW;   // 6912
static constexpr int SMEM_HALFS = MAIN_HALFS + YBUF_HALFS; // 31520
static constexpr int SMEM_BYTES = SMEM_HALFS * 2;          // 63040 B

static constexpr int THREADS = 512;                   // 1 px/thread

__device__ __forceinline__ __half2 u2h(unsigned u) {
    return *reinterpret_cast<__half2*>(&u);
}

// Fetch 48 B (both x-corners, 12 ch) from a y-lerped row slab, x-lerp -> 6 half2.
__device__ __forceinline__ void fetch_xlerp(const __half* buf, int off,
                                            __half2 wx0, __half2 wx1,
                                            __half2* r) {
    const uint2* p = reinterpret_cast<const uint2*>(buf + off);
    uint2 a0 = p[0], a1 = p[1], a2 = p[2];   // corner ix0
    uint2 b0 = p[3], b1 = p[4], b2 = p[5];   // corner ix0+1 (pad if edge, wx1=0)
    r[0] = __hfma2(u2h(b0.x), wx1, __hmul2(u2h(a0.x), wx0));
    r[1] = __hfma2(u2h(b0.y), wx1, __hmul2(u2h(a0.y), wx0));
    r[2] = __hfma2(u2h(b1.x), wx1, __hmul2(u2h(a1.x), wx0));
    r[3] = __hfma2(u2h(b1.y), wx1, __hmul2(u2h(a1.y), wx0));
    r[4] = __hfma2(u2h(b2.x), wx1, __hmul2(u2h(a2.x), wx0));
    r[5] = __hfma2(u2h(b2.y), wx1, __hmul2(u2h(a2.y), wx0));
}

__global__ __launch_bounds__(THREADS, 3)
void slice_kernel(const float* __restrict__ grid,
                  const float* __restrict__ guide,
                  float* __restrict__ out) {
    extern __shared__ __align__(16) __half sh[];
    __half* yb = sh + MAIN_HALFS;    // [row][z][x][c] y-lerped buffer

    const int n      = blockIdx.y;
    const int tid    = threadIdx.x;
    const int seg    = blockIdx.x & 1;
    const int rowblk = blockIdx.x >> 1;
    const int row0   = rowblk * ROWS_PER_BLOCK;

    // ---- Phase 1: load grid[n] (c,z,y,x) f32 -> sh half (z, y*16+x, c);
    //      also zero the ybuf pads (written once, never overwritten). ----
    const float* g = grid + (size_t)n * GRID_PER_N;
    #pragma unroll
    for (int i = tid * 4; i < GRID_PER_N; i += THREADS * 4) {
        float4 v = *reinterpret_cast<const float4*>(g + i);
        int c   = i >> 11;
        int zyx = i & 2047;
        int z   = zyx >> 8;
        int yx  = zyx & 255;
        int base = z * ZSTRIDE_H + yx * C + c;
        sh[base]         = __float2half_rn(v.x);
        sh[base + C]     = __float2half_rn(v.y);
        sh[base + 2 * C] = __float2half_rn(v.z);
        sh[base + 3 * C] = __float2half_rn(v.w);
    }
    // pads: ROWS*8*12 = 384 half2
    if (tid < ROWS_PER_BLOCK * GD * 12) {
        int r  = tid / (GD * 12);
        int rm = tid - r * (GD * 12);
        int z  = rm / 12;
        int t  = rm - z * 12;
        *reinterpret_cast<__half2*>(yb + r * YROW + z * YZS + 192 + 2 * t) =
            __float2half2_rn(0.0f);
    }
    __syncthreads();

    // ---- Phase 2: y-lerp all 4 rows into ybuf (3072 half2, 6 iters) ----
    #pragma unroll
    for (int k = 0; k < 6; ++k) {
        int e   = tid + k * THREADS;        // [0, 3072)
        int r   = e / 768;                  // row within block
        int rem = e - r * 768;
        int z   = rem / 96;
        int q   = rem - z * 96;             // half2 index within (row,z): [0,96)

        int row = row0 + r;
        float ty = (row + 0.5f) * (16.0f / 1024.0f) - 0.5f;
        float fy = floorf(ty);
        float by = ty - fy;
        int ify = (int)fy;
        int iy0 = min(max(ify, 0), GH - 1);
        int iy1 = min(max(ify + 1, 0), GH - 1);

        int src = z * ZSTRIDE_H + 2 * q;
        unsigned a = *reinterpret_cast<const unsigned*>(sh + src + iy0 * 192);
        unsigned b = *reinterpret_cast<const unsigned*>(sh + src + iy1 * 192);
        __half2 wy1 = __float2half2_rn(by);
        __half2 wy0 = __float2half2_rn(1.0f - by);
        __half2 v = __hfma2(u2h(b), wy1, __hmul2(u2h(a), wy0));
        *reinterpret_cast<__half2*>(yb + r * YROW + z * YZS + 2 * q) = v;
    }
    __syncthreads();

    // ---- Phase 3: per-pixel, barrier-free across the 4 rows ----
    const int x = seg * 512 + tid;

    float tx = (x + 0.5f) * (1.0f / 64.0f) - 0.5f;
    float fx = floorf(tx);
    int  ifx = (int)fx;
    float bx = tx - fx;
    float w1f = (ifx < 0 || ifx >= GW - 1) ? 0.0f : bx;
    const __half2 wx0 = __float2half2_rn(1.0f - w1f);
    const __half2 wx1 = __float2half2_rn(w1f);
    const int xoff = min(max(ifx, 0), GW - 1) * C;

    const float* gd = guide + (size_t)n * HW + x;
    float* ob = out + (size_t)n * C * HW + x;

    #pragma unroll
    for (int j = 0; j < ROWS_PER_BLOCK; ++j) {
        const int row = row0 + j;
        const __half* rbuf = yb + j * YROW;

        float gz = gd[(size_t)row * W];
        float tz = gz * 8.0f - 0.5f;
        float fz = floorf(tz);
        float bz = tz - fz;
        int ifz = (int)fz;
        int iz0 = min(max(ifz, 0), GD - 1);
        int iz1 = min(max(ifz + 1, 0), GD - 1);
        const __half2 wz0 = __float2half2_rn(1.0f - bz);
        const __half2 wz1 = __float2half2_rn(bz);

        __half2 v0[6], v1[6];
        fetch_xlerp(rbuf, iz0 * YZS + xoff, wx0, wx1, v0);
        fetch_xlerp(rbuf, iz1 * YZS + xoff, wx0, wx1, v1);

        float* obr = ob + (size_t)row * W;
        #pragma unroll
        for (int k = 0; k < 6; ++k) {
            __half2 vz = __hfma2(v1[k], wz1, __hmul2(v0[k], wz0));
            float2 f = __half22float2(vz);
            obr[(size_t)(2 * k) * HW]     = f.x;
            obr[(size_t)(2 * k + 1) * HW] = f.y;
        }
    }
}

extern "C" void kernel_launch(void* const* d_in, const int* in_sizes, int n_in,
                              void* d_out, int out_size) {
    const float* grid  = (const float*)d_in[0];   // (4,12,8,16,16) f32
    const float* guide = (const float*)d_in[1];   // (4,1,1024,1024) f32
    float* out = (float*)d_out;                   // (4,12,1024,1024) f32

    cudaFuncSetAttribute(slice_kernel,
                         cudaFuncAttributeMaxDynamicSharedMemorySize,
                         SMEM_BYTES);

    dim3 gridDim((H / ROWS_PER_BLOCK) * 2, Nb);   // (512, 4) = 2048 blocks
    slice_kernel<<<gridDim, THREADS, SMEM_BYTES>>>(grid, guide, out);
}

// round 9
// speedup vs baseline: 1.7434x; 1.0058x over previous
#include <cuda_runtime.h>
#include <cuda_fp16.h>
#include <cstdint>

// Problem constants
static constexpr int Nb = 4, C = 12, GD = 8, GH = 16, GW = 16;
static constexpr int H = 1024, W = 1024;
static constexpr int HW = H * W;
static constexpr int GRID_PER_N = C * GD * GH * GW;   // 24576 floats

// Main grid (half) layout [z][y*16+x][c], z-stride padded to 3076 halfs
// (1538 words == 2 mod 32 -> 8 z levels on disjoint bank pairs).
static constexpr int ZSTRIDE_H = GH * GW * C + 4;     // 3076 halfs
static constexpr int MAIN_HALFS = GD * ZSTRIDE_H;     // 24608 halfs

// y-lerped buffer: [row][z][x-entry][16 halfs]. Entry = 12 data + 4 pad halfs
// (32 B) so corner fetches are LDS.128 + LDS.64 at 16B-aligned addresses.
// z-slab = 16 entries + 8 pad halfs = 264 halfs = 132 words == 4 (mod 32):
// the 8 z levels hit disjoint 4-word bank groups -> conflict-free.
static constexpr int ENTRY = 16;                       // halfs per x entry
static constexpr int YSLAB = GW * ENTRY + 8;           // 264 halfs
static constexpr int YROW  = GD * YSLAB;               // 2112 halfs
static constexpr int ROWS_PER_BLOCK = 2;
static constexpr int YBUF_HALFS = ROWS_PER_BLOCK * YROW + 16;  // 4240 (tail pad)
static constexpr int SMEM_HALFS = MAIN_HALFS + YBUF_HALFS;     // 28848
static constexpr int SMEM_BYTES = SMEM_HALFS * 2;              // 57696 B

static constexpr int THREADS = 512;                    // 2 px/thread = full row

__device__ __forceinline__ __half2 u2h(unsigned u) {
    return *reinterpret_cast<__half2*>(&u);
}

// Fetch both x-corners (12 ch each) from a y-lerped slab and x-lerp -> 6 half2.
// off is in halfs, multiple of 16 (entry-aligned).
__device__ __forceinline__ void fetch_xlerp(const __half* buf, int off,
                                            __half2 wx0, __half2 wx1,
                                            __half2* r) {
    uint4 a01 = *reinterpret_cast<const uint4*>(buf + off);        // ch0..7
    uint2 a2  = *reinterpret_cast<const uint2*>(buf + off + 8);    // ch8..11
    uint4 b01 = *reinterpret_cast<const uint4*>(buf + off + ENTRY);
    uint2 b2  = *reinterpret_cast<const uint2*>(buf + off + ENTRY + 8);
    r[0] = __hfma2(u2h(b01.x), wx1, __hmul2(u2h(a01.x), wx0));
    r[1] = __hfma2(u2h(b01.y), wx1, __hmul2(u2h(a01.y), wx0));
    r[2] = __hfma2(u2h(b01.z), wx1, __hmul2(u2h(a01.z), wx0));
    r[3] = __hfma2(u2h(b01.w), wx1, __hmul2(u2h(a01.w), wx0));
    r[4] = __hfma2(u2h(b2.x),  wx1, __hmul2(u2h(a2.x),  wx0));
    r[5] = __hfma2(u2h(b2.y),  wx1, __hmul2(u2h(a2.y),  wx0));
}

__global__ __launch_bounds__(THREADS, 3)
void slice_kernel(const float* __restrict__ grid,
                  const float* __restrict__ guide,
                  float* __restrict__ out) {
    extern __shared__ __align__(16) __half sh[];
    __half* yb = sh + MAIN_HALFS;

    const int n    = blockIdx.y;
    const int tid  = threadIdx.x;
    const int row0 = blockIdx.x * ROWS_PER_BLOCK;

    // ---- Phase 1: grid[n] (c,z,y,x) f32 -> sh half (z, y*16+x, c) ----
    // Channel-pair scheme: load float2 from rows c and c+1 at the same x-pair,
    // emit two half2 (channels c,c+1 for x and x+1). 12 iters/thread.
    const float* g = grid + (size_t)n * GRID_PER_N;
    #pragma unroll
    for (int k = 0; k < 12; ++k) {
        int e    = tid + k * THREADS;       // [0, 6144)
        int c2   = e >> 10;                 // channel pair 0..5
        int zyx2 = e & 1023;                // x-pair index
        int zyx  = zyx2 * 2;
        int z    = zyx >> 8;
        int yx   = zyx & 255;
        const float* base = g + (size_t)(2 * c2) * 2048 + zyx;
        float2 a = *reinterpret_cast<const float2*>(base);          // ch c
        float2 b = *reinterpret_cast<const float2*>(base + 2048);   // ch c+1
        int dst = z * ZSTRIDE_H + yx * C + 2 * c2;
        *reinterpret_cast<__half2*>(sh + dst)     = __floats2half2_rn(a.x, b.x);
        *reinterpret_cast<__half2*>(sh + dst + C) = __floats2half2_rn(a.y, b.y);
    }
    // Zero entire ybuf (pads never overwritten afterwards)
    #pragma unroll
    for (int e = tid; e < YBUF_HALFS / 2; e += THREADS)
        *reinterpret_cast<unsigned*>(yb + 2 * e) = 0u;
    __syncthreads();

    // ---- Phase 2: y-lerp both rows into ybuf (1536 half2, 3 iters) ----
    #pragma unroll
    for (int k = 0; k < 3; ++k) {
        int e   = tid + k * THREADS;        // [0, 1536)
        int r   = e / 768;
        int rem = e - r * 768;
        int z   = rem / 96;
        int q   = rem - z * 96;             // q = x*6 + c2
        int x   = q / 6;
        int c2  = q - x * 6;

        int row = row0 + r;
        float ty = (row + 0.5f) * (16.0f / 1024.0f) - 0.5f;
        float fy = floorf(ty);
        float by = ty - fy;
        int ify = (int)fy;
        int iy0 = min(max(ify, 0), GH - 1);
        int iy1 = min(max(ify + 1, 0), GH - 1);

        int src = z * ZSTRIDE_H + 2 * q;
        unsigned a = *reinterpret_cast<const unsigned*>(sh + src + iy0 * 192);
        unsigned b = *reinterpret_cast<const unsigned*>(sh + src + iy1 * 192);
        __half2 v = __hfma2(u2h(b), __float2half2_rn(by),
                            __hmul2(u2h(a), __float2half2_rn(1.0f - by)));
        *reinterpret_cast<__half2*>(yb + r * YROW + z * YSLAB
                                    + x * ENTRY + 2 * c2) = v;
    }
    __syncthreads();

    // ---- Phase 3: 2 px/thread, barrier-free ----
    const int x0 = tid * 2;                 // pair never crosses a cell edge

    float tx = (x0 + 0.5f) * (1.0f / 64.0f) - 0.5f;
    float fx = floorf(tx);
    int  ifx = (int)fx;
    float bx0 = tx - fx;
    bool edge = (ifx < 0 || ifx >= GW - 1);
    float w1a = edge ? 0.0f : bx0;
    float w1b = edge ? 0.0f : bx0 + (1.0f / 64.0f);
    const int xoff = min(max(ifx, 0), GW - 1) * ENTRY;

    const float* gd = guide + (size_t)n * HW + x0;
    float* ob = out + (size_t)n * C * HW + x0;

    #pragma unroll
    for (int j = 0; j < ROWS_PER_BLOCK; ++j) {
        const int row = row0 + j;
        const __half* rbuf = yb + j * YROW;

        float2 gz = *reinterpret_cast<const float2*>(gd + (size_t)row * W);

        __half2 vz0[6], vz1[6];
        #pragma unroll
        for (int p = 0; p < 2; ++p) {
            float tz = (p ? gz.y : gz.x) * 8.0f - 0.5f;
            float fz = floorf(tz);
            float bz = tz - fz;
            int ifz = (int)fz;
            int iz0 = min(max(ifz, 0), GD - 1);
            int iz1 = min(max(ifz + 1, 0), GD - 1);
            float w1 = p ? w1b : w1a;
            __half2 wx1 = __float2half2_rn(w1);
            __half2 wx0 = __float2half2_rn(1.0f - w1);
            __half2 wz0h = __float2half2_rn(1.0f - bz);
            __half2 wz1h = __float2half2_rn(bz);

            __half2 r0[6], r1[6];
            fetch_xlerp(rbuf, iz0 * YSLAB + xoff, wx0, wx1, r0);
            fetch_xlerp(rbuf, iz1 * YSLAB + xoff, wx0, wx1, r1);
            __half2* vz = p ? vz1 : vz0;
            #pragma unroll
            for (int kk = 0; kk < 6; ++kk)
                vz[kk] = __hfma2(r1[kk], wz1h, __hmul2(r0[kk], wz0h));
        }

        // 12 STG.64: channel-major, {px0, px1} pairs
        float* obr = ob + (size_t)row * W;
        #pragma unroll
        for (int kk = 0; kk < 6; ++kk) {
            float2 fa = __half22float2(vz0[kk]);   // (ch 2k, 2k+1) px0
            float2 fb = __half22float2(vz1[kk]);   // (ch 2k, 2k+1) px1
            float2 lo = make_float2(fa.x, fb.x);   // channel 2k
            float2 hi = make_float2(fa.y, fb.y);   // channel 2k+1
            *reinterpret_cast<float2*>(obr + (size_t)(2 * kk) * HW)     = lo;
            *reinterpret_cast<float2*>(obr + (size_t)(2 * kk + 1) * HW) = hi;
        }
    }
}

extern "C" void kernel_launch(void* const* d_in, const int* in_sizes, int n_in,
                              void* d_out, int out_size) {
    const float* grid  = (const float*)d_in[0];   // (4,12,8,16,16) f32
    const float* guide = (const float*)d_in[1];   // (4,1,1024,1024) f32
    float* out = (float*)d_out;                   // (4,12,1024,1024) f32

    cudaFuncSetAttribute(slice_kernel,
                         cudaFuncAttributeMaxDynamicSharedMemorySize,
                         SMEM_BYTES);

    dim3 gridDim(H / ROWS_PER_BLOCK, Nb);         // (512, 4) = 2048 blocks
    slice_kernel<<<gridDim, THREADS, SMEM_BYTES>>>(grid, guide, out);
}